// round 8
// baseline (speedup 1.0000x reference)
#include <cuda_runtime.h>
#include <cuda_bf16.h>

// Problem shape (fixed by the dataset's setup_inputs)
#define BB 4
#define LL 4096
#define MM 2048
#define DD 2048
#define D4 (DD / 4)        // 512 float4 lanes
#define CC 128             // chunks along M
#define TT 16              // chunk length = MM / CC
#define HT 8               // half-tile (register batch depth)
#define NSUP 8             // superchunks
#define SUPLEN 16          // chunks per superchunk
#define EPSF 1e-4f

// Scratch (device globals: no allocation allowed in kernel_launch)
__device__ float4 g_PADT[BB * MM];          // per (b,t): {p, a=1-p, dt, 1/dt}
__device__ int    g_POS [BB * MM];          // position l of the t-th boundary
__device__ int    g_count[BB];              // boundaries per batch
__device__ float  g_P   [BB * CC];          // per-chunk product of a
__device__ float  g_W   [BB * CC];          // prefix product within superchunk
__device__ float  g_V   [BB * NSUP * NSUP]; // superchunk combine weights
__device__ float4 g_S4  [BB * CC * D4];     // per-chunk partial (zero carry-in)
__device__ float4 g_Hin4[BB * CC * D4];     // carry-in LOCAL to superchunk
__device__ float4 g_Ssup[BB * NSUP * D4];   // superchunk partial (zero carry-in)

// ---------------------------------------------------------------------------
// Setup: boundary scan, p gather (stable-sort semantics), scalar products.
// One block per batch, 512 threads, 8 tokens each.
// ---------------------------------------------------------------------------
__global__ void setup_kernel(const float* __restrict__ bp,
                             const void*  __restrict__ mask_raw)
{
    const int b   = blockIdx.x;
    const int tid = threadIdx.x;

    __shared__ int   s_is32;
    __shared__ int   s_cnt[512];
    __shared__ float s_a[MM];       // a = 1-p by sorted slot
    __shared__ float s_prod[CC];    // per-chunk products
    __shared__ float s_psup[NSUP];  // per-superchunk products

    // Probe mask dtype: int32 bools -> first 64 words all in {0,1};
    // packed uint8 bools (mixed pattern) -> some word > 1.
    if (tid == 0) {
        const int* w = (const int*)mask_raw;
        int ok = 1;
        for (int i = 0; i < 64; i++) {
            unsigned v = (unsigned)w[i];
            if (v > 1u) { ok = 0; break; }
        }
        s_is32 = ok;
    }
    __syncthreads();
    const bool is32 = (s_is32 != 0);

    int flags[8];
    const int base_l = tid * 8;
    int cnt = 0;
#pragma unroll
    for (int i = 0; i < 8; i++) {
        const int l = base_l + i;
        int f;
        if (is32) f = (((const int*)mask_raw)[b * LL + l] != 0);
        else      f = (((const unsigned char*)mask_raw)[b * LL + l] != 0);
        flags[i] = f;
        cnt += f;
    }
    s_cnt[tid] = cnt;
    __syncthreads();

    // Hillis-Steele inclusive scan over 512 per-thread counts
    for (int off = 1; off < 512; off <<= 1) {
        int v   = s_cnt[tid];
        int add = (tid >= off) ? s_cnt[tid - off] : 0;
        __syncthreads();
        s_cnt[tid] = v + add;
        __syncthreads();
    }
    const int total = s_cnt[511];
    int run = s_cnt[tid] - cnt;    // boundaries strictly before my first token
    if (tid == 0) g_count[b] = total;

    // Stable-sort position: boundaries first (in order), then non-boundaries.
#pragma unroll
    for (int i = 0; i < 8; i++) {
        const int l = base_l + i;
        int s;
        if (flags[i]) { s = run; run++; }
        else          { s = total + (l - run); }
        if (s < MM) {
            float p = bp[b * LL + l];
            p = fminf(fmaxf(p, EPSF), 1.0f - EPSF);
            const float a     = 1.0f - p;
            const float dt    = logf(1.0f / a);
            const float invdt = 1.0f / dt;
            g_PADT[b * MM + s] = make_float4(p, a, dt, invdt);
            s_a[s] = a;
            if (flags[i]) g_POS[b * MM + s] = l;
        }
    }
    __syncthreads();

    // Per-chunk products of a from smem (a <= 1-eps; underflow benign)
    if (tid < CC) {
        float prod = 1.0f;
#pragma unroll
        for (int i = 0; i < TT; i++) prod *= s_a[tid * TT + i];
        s_prod[tid] = prod;
        g_P[b * CC + tid] = prod;
    }
    __syncthreads();

    // Prefix product within superchunk: W_c = prod over chunks [sup_start, c)
    if (tid < CC) {
        const int s0 = (tid / SUPLEN) * SUPLEN;
        float w = 1.0f;
        for (int k = s0; k < tid; k++) w *= s_prod[k];
        g_W[b * CC + tid] = w;
    }
    // Superchunk product
    if (tid < NSUP) {
        float ps = 1.0f;
#pragma unroll
        for (int k = 0; k < SUPLEN; k++) ps *= s_prod[tid * SUPLEN + k];
        s_psup[tid] = ps;
    }
    __syncthreads();

    // Superchunk combine weights: V[s][s'] = prod Psup over (s', s); 0 if s'>=s.
    // Hsup[s] = sum_{s'<s} V[s][s'] * Ssup[s']  (expanded superchunk scan)
    if (tid < NSUP * NSUP) {
        const int s  = tid / NSUP;
        const int sp = tid % NSUP;
        float v = 0.0f;
        if (sp < s) {
            v = 1.0f;
            for (int k = sp + 1; k < s; k++) v *= s_psup[k];
        }
        g_V[(b * NSUP + s) * NSUP + sp] = v;
    }
}

// ---------------------------------------------------------------------------
// Pass 1: per-chunk partial EMA with zero carry-in -> g_S4.
// Grid (D4/256, CC, BB). Two 8-deep load batches: MLP with lower reg tile.
// ---------------------------------------------------------------------------
__global__ void pass1_kernel(const float4* __restrict__ hid4)
{
    const int d4 = blockIdx.x * 256 + threadIdx.x;
    const int c  = blockIdx.y;
    const int b  = blockIdx.z;

    __shared__ float4 sp[TT];
    if (threadIdx.x < TT)
        sp[threadIdx.x] = g_PADT[b * MM + c * TT + threadIdx.x];
    __syncthreads();

    const float4* hptr = hid4 + (size_t)(b * MM + c * TT) * D4 + d4;
    float4 S = make_float4(0.f, 0.f, 0.f, 0.f);

#pragma unroll 1
    for (int half = 0; half < TT / HT; half++) {
        float4 hv[HT];
#pragma unroll
        for (int j = 0; j < HT; j++)
            hv[j] = __ldcg(hptr + (size_t)(half * HT + j) * D4);
#pragma unroll
        for (int j = 0; j < HT; j++) {
            const float4 q = sp[half * HT + j];
            S.x = fmaf(q.y, S.x, q.x * ((hv[j].x * q.w) * q.z));
            S.y = fmaf(q.y, S.y, q.x * ((hv[j].y * q.w) * q.z));
            S.z = fmaf(q.y, S.z, q.x * ((hv[j].z * q.w) * q.z));
            S.w = fmaf(q.y, S.w, q.x * ((hv[j].w * q.w) * q.z));
        }
    }
    __stcg(&g_S4[(b * CC + c) * D4 + d4], S);    // keep in L2 for pass2a
}

// ---------------------------------------------------------------------------
// Pass 2a: within-superchunk scan. Grid (D4/256, NSUP, BB) = 64 blocks.
// Produces carry-in LOCAL to the superchunk + superchunk aggregate.
// ---------------------------------------------------------------------------
__global__ void pass2a_kernel()
{
    const int d4 = blockIdx.x * 256 + threadIdx.x;
    const int s  = blockIdx.y;
    const int b  = blockIdx.z;

    __shared__ float sP[SUPLEN];
    if (threadIdx.x < SUPLEN)
        sP[threadIdx.x] = g_P[b * CC + s * SUPLEN + threadIdx.x];
    __syncthreads();

    const int base = (b * CC + s * SUPLEN) * D4 + d4;
    float4 h = make_float4(0.f, 0.f, 0.f, 0.f);

#pragma unroll 1
    for (int half = 0; half < SUPLEN / HT; half++) {
        float4 Sv[HT];
#pragma unroll
        for (int j = 0; j < HT; j++)
            Sv[j] = __ldcg(&g_S4[base + (half * HT + j) * D4]);
#pragma unroll
        for (int j = 0; j < HT; j++) {
            __stcg(&g_Hin4[base + (half * HT + j) * D4], h);  // L2 for pass3
            const float P = sP[half * HT + j];
            h.x = fmaf(P, h.x, Sv[j].x);
            h.y = fmaf(P, h.y, Sv[j].y);
            h.z = fmaf(P, h.z, Sv[j].z);
            h.w = fmaf(P, h.w, Sv[j].w);
        }
    }
    __stcg(&g_Ssup[(b * NSUP + s) * D4 + d4], h);
}

// ---------------------------------------------------------------------------
// Pass 3: recompute in-chunk states with full carry-in, expand to out.
// h_in = Hin_local + W_c * sum_{s'<sup} V[sup][s'] * Ssup[s']
// Two 8-deep hv batches keep regs low (occupancy) with 8-way MLP each.
// ---------------------------------------------------------------------------
__global__ void pass3_kernel(const float4* __restrict__ hid4,
                             float4* __restrict__ out4)
{
    const int d4  = blockIdx.x * 256 + threadIdx.x;
    const int c   = blockIdx.y;
    const int b   = blockIdx.z;
    const int tid = threadIdx.x;
    const int sup = c / SUPLEN;      // uniform per block

    __shared__ float4 sp[TT];
    __shared__ int    spos[TT + 1];
    __shared__ int    s_cnt_sh;
    __shared__ float  s_W;
    __shared__ float  s_V[NSUP];

    if (tid < TT) sp[tid] = g_PADT[b * MM + c * TT + tid];
    if (tid <= TT) {
        const int idx = c * TT + tid;
        spos[tid] = (idx < MM) ? g_POS[b * MM + idx] : LL;
    }
    if (tid < NSUP) s_V[tid] = g_V[(b * NSUP + sup) * NSUP + tid];
    if (tid == 255) { s_cnt_sh = min(g_count[b], MM); s_W = g_W[b * CC + c]; }
    __syncthreads();
    const int cnt = s_cnt_sh;
    const float W = s_W;

    // Carry-in: local part + weighted superchunk prefixes (all L2-resident).
    const float4 hloc = __ldcg(&g_Hin4[(b * CC + c) * D4 + d4]);

    float4 acc = make_float4(0.f, 0.f, 0.f, 0.f);
#pragma unroll
    for (int j = 0; j < NSUP - 1; j++) {
        if (j < sup) {
            const float4 sv = __ldcg(&g_Ssup[(b * NSUP + j) * D4 + d4]);
            const float  v  = s_V[j];
            acc.x = fmaf(v, sv.x, acc.x);
            acc.y = fmaf(v, sv.y, acc.y);
            acc.z = fmaf(v, sv.z, acc.z);
            acc.w = fmaf(v, sv.w, acc.w);
        }
    }

    float4 h;
    h.x = fmaf(W, acc.x, hloc.x);
    h.y = fmaf(W, acc.y, hloc.y);
    h.z = fmaf(W, acc.z, hloc.z);
    h.w = fmaf(W, acc.w, hloc.w);

    const float4* hptr = hid4 + (size_t)(b * MM + c * TT) * D4 + d4;
    float4* outb = out4 + (size_t)b * LL * D4 + d4;

#pragma unroll 1
    for (int half = 0; half < TT / HT; half++) {
        float4 hv[HT];
#pragma unroll
        for (int j = 0; j < HT; j++)
            hv[j] = __ldcg(hptr + (size_t)(half * HT + j) * D4);

#pragma unroll
        for (int j = 0; j < HT; j++) {
            const int t = half * HT + j;
            const float4 q = sp[t];
            h.x = fmaf(q.y, h.x, q.x * ((hv[j].x * q.w) * q.z));
            h.y = fmaf(q.y, h.y, q.x * ((hv[j].y * q.w) * q.z));
            h.z = fmaf(q.y, h.z, q.x * ((hv[j].z * q.w) * q.z));
            h.w = fmaf(q.y, h.w, q.x * ((hv[j].w * q.w) * q.z));

            const int tg = c * TT + t;
            if (tg < cnt) {
                const int start = spos[t];
                const int end   = (tg + 1 < cnt) ? spos[t + 1] : LL;
                for (int l = start; l < end; l++) {
                    __stcs(outb + (size_t)l * D4, h);   // streaming 16B store
                }
            }
        }
    }
}

// ---------------------------------------------------------------------------
// Inputs (metadata order = setup_inputs dict order):
//   d_in[0] hidden_states  float32 (B,M,D)
//   d_in[1] boundary_prob  float32 (B,L)
//   d_in[2] boundary_mask  bool    (B,L)  (dtype probed device-side)
//   d_in[3] mask                    -- unused by the reference
// Output: float32 (B,L,D)
// ---------------------------------------------------------------------------
extern "C" void kernel_launch(void* const* d_in, const int* in_sizes, int n_in,
                              void* d_out, int out_size)
{
    const float4* hid4 = (const float4*)d_in[0];
    const float*  bp   = (const float*)d_in[1];
    const void*   bm   = d_in[2];
    float4* out4 = (float4*)d_out;

    setup_kernel<<<BB, 512>>>(bp, bm);
    pass1_kernel<<<dim3(D4 / 256, CC, BB), 256>>>(hid4);
    pass2a_kernel<<<dim3(D4 / 256, NSUP, BB), 256>>>();
    pass3_kernel<<<dim3(D4 / 256, CC, BB), 256>>>(hid4, out4);
}

// round 9
// speedup vs baseline: 1.0695x; 1.0695x over previous
#include <cuda_runtime.h>
#include <cuda_bf16.h>

// Problem shape (fixed by the dataset's setup_inputs)
#define BB 4
#define LL 4096
#define MM 2048
#define DD 2048
#define D4 (DD / 4)        // 512 float4 lanes
#define CC 128             // chunks along M
#define TT 16              // chunk length = MM / CC
#define NSUP 8             // superchunks
#define SUPLEN 16          // chunks per superchunk
#define EPSF 1e-4f

// Scratch (device globals: no allocation allowed in kernel_launch)
__device__ float4 g_PADT[BB * MM];          // per (b,t): {p, a=1-p, dt, 1/dt}
__device__ int    g_POS [BB * MM];          // position l of the t-th boundary
__device__ int    g_count[BB];              // boundaries per batch
__device__ float  g_P   [BB * CC];          // per-chunk product of a
__device__ float  g_W   [BB * CC];          // prefix product within superchunk
__device__ float  g_V   [BB * NSUP * NSUP]; // superchunk combine weights
__device__ float4 g_S4  [BB * CC * D4];     // per-chunk partial (zero carry-in)
__device__ float4 g_Hin4[BB * CC * D4];     // carry-in LOCAL to superchunk
__device__ float4 g_Ssup[BB * NSUP * D4];   // superchunk partial (zero carry-in)

// ---------------------------------------------------------------------------
// Setup: boundary scan, p gather (stable-sort semantics), scalar products.
// One block per batch, 512 threads, 8 tokens each.
// ---------------------------------------------------------------------------
__global__ void setup_kernel(const float* __restrict__ bp,
                             const void*  __restrict__ mask_raw)
{
    const int b   = blockIdx.x;
    const int tid = threadIdx.x;

    __shared__ int   s_is32;
    __shared__ int   s_cnt[512];
    __shared__ float s_a[MM];       // a = 1-p by sorted slot
    __shared__ float s_prod[CC];    // per-chunk products
    __shared__ float s_psup[NSUP];  // per-superchunk products

    // Probe mask dtype: int32 bools -> first 64 words all in {0,1};
    // packed uint8 bools (mixed pattern) -> some word > 1.
    if (tid == 0) {
        const int* w = (const int*)mask_raw;
        int ok = 1;
        for (int i = 0; i < 64; i++) {
            unsigned v = (unsigned)w[i];
            if (v > 1u) { ok = 0; break; }
        }
        s_is32 = ok;
    }
    __syncthreads();
    const bool is32 = (s_is32 != 0);

    int flags[8];
    const int base_l = tid * 8;
    int cnt = 0;
#pragma unroll
    for (int i = 0; i < 8; i++) {
        const int l = base_l + i;
        int f;
        if (is32) f = (((const int*)mask_raw)[b * LL + l] != 0);
        else      f = (((const unsigned char*)mask_raw)[b * LL + l] != 0);
        flags[i] = f;
        cnt += f;
    }
    s_cnt[tid] = cnt;
    __syncthreads();

    // Hillis-Steele inclusive scan over 512 per-thread counts
    for (int off = 1; off < 512; off <<= 1) {
        int v   = s_cnt[tid];
        int add = (tid >= off) ? s_cnt[tid - off] : 0;
        __syncthreads();
        s_cnt[tid] = v + add;
        __syncthreads();
    }
    const int total = s_cnt[511];
    int run = s_cnt[tid] - cnt;    // boundaries strictly before my first token
    if (tid == 0) g_count[b] = total;

    // Stable-sort position: boundaries first (in order), then non-boundaries.
#pragma unroll
    for (int i = 0; i < 8; i++) {
        const int l = base_l + i;
        int s;
        if (flags[i]) { s = run; run++; }
        else          { s = total + (l - run); }
        if (s < MM) {
            float p = bp[b * LL + l];
            p = fminf(fmaxf(p, EPSF), 1.0f - EPSF);
            const float a     = 1.0f - p;
            const float dt    = logf(1.0f / a);
            const float invdt = 1.0f / dt;
            g_PADT[b * MM + s] = make_float4(p, a, dt, invdt);
            s_a[s] = a;
            if (flags[i]) g_POS[b * MM + s] = l;
        }
    }
    __syncthreads();

    // Per-chunk products of a from smem (a <= 1-eps; underflow benign)
    if (tid < CC) {
        float prod = 1.0f;
#pragma unroll
        for (int i = 0; i < TT; i++) prod *= s_a[tid * TT + i];
        s_prod[tid] = prod;
        g_P[b * CC + tid] = prod;
    }
    __syncthreads();

    // Prefix product within superchunk: W_c = prod over chunks [sup_start, c)
    if (tid < CC) {
        const int s0 = (tid / SUPLEN) * SUPLEN;
        float w = 1.0f;
        for (int k = s0; k < tid; k++) w *= s_prod[k];
        g_W[b * CC + tid] = w;
    }
    // Superchunk product
    if (tid < NSUP) {
        float ps = 1.0f;
#pragma unroll
        for (int k = 0; k < SUPLEN; k++) ps *= s_prod[tid * SUPLEN + k];
        s_psup[tid] = ps;
    }
    __syncthreads();

    // Superchunk combine weights: V[s][s'] = prod Psup over (s', s); 0 if s'>=s.
    // Hsup[s] = sum_{s'<s} V[s][s'] * Ssup[s']  (expanded superchunk scan)
    if (tid < NSUP * NSUP) {
        const int s  = tid / NSUP;
        const int sp = tid % NSUP;
        float v = 0.0f;
        if (sp < s) {
            v = 1.0f;
            for (int k = sp + 1; k < s; k++) v *= s_psup[k];
        }
        g_V[(b * NSUP + s) * NSUP + sp] = v;
    }
}

// ---------------------------------------------------------------------------
// Pass 1: per-chunk partial EMA with zero carry-in -> g_S4.
// Grid (D4/256, CC, BB). Tile loads front-batched 16-deep (R7 config).
// ---------------------------------------------------------------------------
__global__ void pass1_kernel(const float4* __restrict__ hid4)
{
    const int d4 = blockIdx.x * 256 + threadIdx.x;
    const int c  = blockIdx.y;
    const int b  = blockIdx.z;

    __shared__ float4 sp[TT];
    if (threadIdx.x < TT)
        sp[threadIdx.x] = g_PADT[b * MM + c * TT + threadIdx.x];
    __syncthreads();

    const float4* hptr = hid4 + (size_t)(b * MM + c * TT) * D4 + d4;
    float4 hv[TT];
#pragma unroll
    for (int t = 0; t < TT; t++)
        hv[t] = __ldcg(hptr + (size_t)t * D4);   // allocate in L2 for pass3

    float4 S = make_float4(0.f, 0.f, 0.f, 0.f);
#pragma unroll
    for (int t = 0; t < TT; t++) {
        const float4 q = sp[t];
        S.x = fmaf(q.y, S.x, q.x * ((hv[t].x * q.w) * q.z));
        S.y = fmaf(q.y, S.y, q.x * ((hv[t].y * q.w) * q.z));
        S.z = fmaf(q.y, S.z, q.x * ((hv[t].z * q.w) * q.z));
        S.w = fmaf(q.y, S.w, q.x * ((hv[t].w * q.w) * q.z));
    }
    __stcg(&g_S4[(b * CC + c) * D4 + d4], S);    // keep in L2 for pass2a
}

// ---------------------------------------------------------------------------
// Pass 2a: within-superchunk scan. 128-thread blocks -> 128 blocks (more
// latency-hiding contexts for this L2-resident 16.5 MB pass).
// ---------------------------------------------------------------------------
__global__ void pass2a_kernel()
{
    const int d4 = blockIdx.x * 128 + threadIdx.x;
    const int s  = blockIdx.y;
    const int b  = blockIdx.z;

    __shared__ float sP[SUPLEN];
    if (threadIdx.x < SUPLEN)
        sP[threadIdx.x] = g_P[b * CC + s * SUPLEN + threadIdx.x];
    __syncthreads();

    const int base = (b * CC + s * SUPLEN) * D4 + d4;
    float4 Sv[SUPLEN];
#pragma unroll
    for (int j = 0; j < SUPLEN; j++)
        Sv[j] = __ldcg(&g_S4[base + j * D4]);

    float4 h = make_float4(0.f, 0.f, 0.f, 0.f);
#pragma unroll
    for (int j = 0; j < SUPLEN; j++) {
        __stcg(&g_Hin4[base + j * D4], h);       // L2-resident for pass3
        const float P = sP[j];
        h.x = fmaf(P, h.x, Sv[j].x);
        h.y = fmaf(P, h.y, Sv[j].y);
        h.z = fmaf(P, h.z, Sv[j].z);
        h.w = fmaf(P, h.w, Sv[j].w);
    }
    __stcg(&g_Ssup[(b * NSUP + s) * D4 + d4], h);
}

// ---------------------------------------------------------------------------
// Pass 3: recompute in-chunk states with full carry-in, expand to out.
// h_in = Hin_local + W_c * sum_{s'<sup} V[sup][s'] * Ssup[s']
// hv loads use __ldcs (LAST use: evict-first frees L2 lines for the write
// stream). 16-deep front batch (R7 config). Streaming 16B output stores.
// ---------------------------------------------------------------------------
__global__ void pass3_kernel(const float4* __restrict__ hid4,
                             float4* __restrict__ out4)
{
    const int d4  = blockIdx.x * 256 + threadIdx.x;
    const int c   = blockIdx.y;
    const int b   = blockIdx.z;
    const int tid = threadIdx.x;
    const int sup = c / SUPLEN;      // uniform per block

    __shared__ float4 sp[TT];
    __shared__ int    spos[TT + 1];
    __shared__ int    s_cnt_sh;
    __shared__ float  s_W;
    __shared__ float  s_V[NSUP];

    if (tid < TT) sp[tid] = g_PADT[b * MM + c * TT + tid];
    if (tid <= TT) {
        const int idx = c * TT + tid;
        spos[tid] = (idx < MM) ? g_POS[b * MM + idx] : LL;
    }
    if (tid < NSUP) s_V[tid] = g_V[(b * NSUP + sup) * NSUP + tid];
    if (tid == 255) { s_cnt_sh = min(g_count[b], MM); s_W = g_W[b * CC + c]; }
    __syncthreads();
    const int cnt = s_cnt_sh;
    const float W = s_W;

    // Front-batch ALL independent loads: local carry, Ssup prefixes, hv tile.
    const float4 hloc = __ldcg(&g_Hin4[(b * CC + c) * D4 + d4]);

    float4 ssv[NSUP - 1];
#pragma unroll
    for (int j = 0; j < NSUP - 1; j++) {
        if (j < sup) ssv[j] = __ldcg(&g_Ssup[(b * NSUP + j) * D4 + d4]);
        else         ssv[j] = make_float4(0.f, 0.f, 0.f, 0.f);
    }

    const float4* hptr = hid4 + (size_t)(b * MM + c * TT) * D4 + d4;
    float4 hv[TT];
#pragma unroll
    for (int t = 0; t < TT; t++)
        hv[t] = __ldcs(hptr + (size_t)t * D4);   // last use: evict-first

    // Combine superchunk prefix contributions with scalar weights.
    float4 acc = make_float4(0.f, 0.f, 0.f, 0.f);
#pragma unroll
    for (int j = 0; j < NSUP - 1; j++) {
        const float v = s_V[j];      // 0 for j >= sup
        acc.x = fmaf(v, ssv[j].x, acc.x);
        acc.y = fmaf(v, ssv[j].y, acc.y);
        acc.z = fmaf(v, ssv[j].z, acc.z);
        acc.w = fmaf(v, ssv[j].w, acc.w);
    }

    float4 h;
    h.x = fmaf(W, acc.x, hloc.x);
    h.y = fmaf(W, acc.y, hloc.y);
    h.z = fmaf(W, acc.z, hloc.z);
    h.w = fmaf(W, acc.w, hloc.w);

    float4* outb = out4 + (size_t)b * LL * D4 + d4;

#pragma unroll
    for (int t = 0; t < TT; t++) {
        const float4 q = sp[t];
        h.x = fmaf(q.y, h.x, q.x * ((hv[t].x * q.w) * q.z));
        h.y = fmaf(q.y, h.y, q.x * ((hv[t].y * q.w) * q.z));
        h.z = fmaf(q.y, h.z, q.x * ((hv[t].z * q.w) * q.z));
        h.w = fmaf(q.y, h.w, q.x * ((hv[t].w * q.w) * q.z));

        const int tg = c * TT + t;
        if (tg < cnt) {
            const int start = spos[t];
            const int end   = (tg + 1 < cnt) ? spos[t + 1] : LL;
            for (int l = start; l < end; l++) {
                __stcs(outb + (size_t)l * D4, h);   // streaming 16B store
            }
        }
    }
}

// ---------------------------------------------------------------------------
// Inputs (metadata order = setup_inputs dict order):
//   d_in[0] hidden_states  float32 (B,M,D)
//   d_in[1] boundary_prob  float32 (B,L)
//   d_in[2] boundary_mask  bool    (B,L)  (dtype probed device-side)
//   d_in[3] mask                    -- unused by the reference
// Output: float32 (B,L,D)
// ---------------------------------------------------------------------------
extern "C" void kernel_launch(void* const* d_in, const int* in_sizes, int n_in,
                              void* d_out, int out_size)
{
    const float4* hid4 = (const float4*)d_in[0];
    const float*  bp   = (const float*)d_in[1];
    const void*   bm   = d_in[2];
    float4* out4 = (float4*)d_out;

    setup_kernel<<<BB, 512>>>(bp, bm);
    pass1_kernel<<<dim3(D4 / 256, CC, BB), 256>>>(hid4);
    pass2a_kernel<<<dim3(D4 / 128, NSUP, BB), 128>>>();
    pass3_kernel<<<dim3(D4 / 256, CC, BB), 256>>>(hid4, out4);
}